// round 5
// baseline (speedup 1.0000x reference)
#include <cuda_runtime.h>
#include <cstdint>

#define SEQ    4096
#define NPOS   8192
#define HEADS  16
#define DIM    64
#define DD     64
#define NCOLS_A 1024
#define ASTR   4104

__device__ float  g_abuf[(size_t)NCOLS_A * NPOS];
__device__ float2 g_Aspec[(size_t)NCOLS_A * ASTR];
__device__ float  g_xt[(size_t)128 * DIM * SEQ];

#define IDX(i) ((i) + ((i) >> 3))
#define SMEM_ELEMS 4608
#define SMEM_BYTES (2 * SMEM_ELEMS * (int)sizeof(float2))

// ---------- packed f32x2 helpers (Blackwell FFMA2 path, PTX-only) ----------
typedef unsigned long long u64;
__device__ __forceinline__ u64 pk2(float lo, float hi){
    u64 r; asm("mov.b64 %0, {%1, %2};" : "=l"(r) : "f"(lo), "f"(hi)); return r;
}
__device__ __forceinline__ void upk2(u64 v, float& lo, float& hi){
    asm("mov.b64 {%0, %1}, %2;" : "=f"(lo), "=f"(hi) : "l"(v));
}
__device__ __forceinline__ u64 fma2(u64 a, u64 b, u64 c){
    u64 d; asm("fma.rn.f32x2 %0, %1, %2, %3;" : "=l"(d) : "l"(a), "l"(b), "l"(c)); return d;
}

__device__ __forceinline__ float2 cadd(float2 a, float2 b){ return make_float2(a.x+b.x, a.y+b.y); }
__device__ __forceinline__ float2 csub(float2 a, float2 b){ return make_float2(a.x-b.x, a.y-b.y); }
__device__ __forceinline__ float2 cmul(float2 a, float2 b){
    return make_float2(a.x*b.x - a.y*b.y, a.x*b.y + a.y*b.x);
}
template<int DIR>
__device__ __forceinline__ float2 mul_i(float2 z){
    return make_float2(-(float)DIR * z.y, (float)DIR * z.x);
}

template<int DIR>
__device__ __forceinline__ void dft4(float2 c0, float2 c1, float2 c2, float2 c3,
                                     float2& d0, float2& d1, float2& d2, float2& d3){
    float2 e0 = cadd(c0,c2), e1 = csub(c0,c2);
    float2 f0 = cadd(c1,c3), f1 = csub(c1,c3);
    float2 t  = mul_i<DIR>(f1);
    d0 = cadd(e0,f0); d2 = csub(e0,f0);
    d1 = cadd(e1,t);  d3 = csub(e1,t);
}

template<int DIR>
__device__ __forceinline__ void dft8(float2 a[8]){
    float2 e0,e1,e2,e3,o0,o1,o2,o3;
    dft4<DIR>(a[0],a[2],a[4],a[6], e0,e1,e2,e3);
    dft4<DIR>(a[1],a[3],a[5],a[7], o0,o1,o2,o3);
    const float C = 0.70710678118654752f;
    float2 w1 = make_float2( C, (float)DIR * C);
    float2 w3 = make_float2(-C, (float)DIR * C);
    float2 t1 = cmul(o1, w1);
    float2 t2 = mul_i<DIR>(o2);
    float2 t3 = cmul(o3, w3);
    a[0] = cadd(e0,o0); a[4] = csub(e0,o0);
    a[1] = cadd(e1,t1); a[5] = csub(e1,t1);
    a[2] = cadd(e2,t2); a[6] = csub(e2,t2);
    a[3] = cadd(e3,t3); a[7] = csub(e3,t3);
}

// Stockham radix-8 stage: 512 butterflies, thread t does one.
template<int DIR>
__device__ __forceinline__ void fft_stage(const float2* __restrict__ in, float2* __restrict__ out,
                                          int n, int s, int t){
    int p = t / s;
    int q = t - p * s;
    float2 a[8];
#pragma unroll
    for (int k = 0; k < 8; k++) a[k] = in[IDX(t + 512*k)];
    dft8<DIR>(a);
    if (p != 0) {
        float base = (float)DIR * 6.283185307179586f / (float)n;
#pragma unroll
        for (int k = 1; k < 8; k++) {
            int r = (p * k) & (n - 1);
            float sn, cs;
            __sincosf(base * (float)r, &sn, &cs);
            a[k] = cmul(a[k], make_float2(cs, sn));
        }
    }
    int ob = q + s * 8 * p;
#pragma unroll
    for (int k = 0; k < 8; k++) out[IDX(ob + s*k)] = a[k];
}

template<int DIR>
__device__ __forceinline__ void run_fft(float2* b0, float2* b1, int t){
    fft_stage<DIR>(b0, b1, 4096,   1, t); __syncthreads();
    fft_stage<DIR>(b1, b0,  512,   8, t); __syncthreads();
    fft_stage<DIR>(b0, b1,   64,  64, t); __syncthreads();
    fft_stage<DIR>(b1, b0,    8, 512, t); __syncthreads();
}

// ------------------------- dpb MLP (f32x2 packed) -------------------------
// h[64] scalar in regs; matmul accumulators packed 2 outputs per u64.
__device__ __forceinline__ void mlp_layer_p(float h[DD], const float* __restrict__ g,
                                            const float* __restrict__ be,
                                            const float* __restrict__ w,
                                            const float* __restrict__ b){
    float m = 0.f;
#pragma unroll
    for (int i = 0; i < DD; i++) m += h[i];
    m *= (1.f/64.f);
    float v = 0.f;
#pragma unroll
    for (int i = 0; i < DD; i++){ float d = h[i]-m; v += d*d; }
    v *= (1.f/64.f);
    float rs = rsqrtf(v + 1e-5f);
#pragma unroll
    for (int i = 0; i < DD; i++) h[i] = fmaxf((h[i]-m)*rs*g[i] + be[i], 0.f);

    u64 acc[DD/2];
    const u64* bu = reinterpret_cast<const u64*>(b);
#pragma unroll
    for (int j = 0; j < DD/2; j++) acc[j] = bu[j];
    for (int i = 0; i < DD; i++){
        u64 rp = pk2(h[i], h[i]);
        const ulonglong2* wr = reinterpret_cast<const ulonglong2*>(w + i*DD);
#pragma unroll
        for (int j = 0; j < 16; j++){
            ulonglong2 wv = wr[j];                 // LDS.128: 2 packed weight pairs
            acc[2*j]   = fma2(rp, wv.x, acc[2*j]);
            acc[2*j+1] = fma2(rp, wv.y, acc[2*j+1]);
        }
    }
#pragma unroll
    for (int j = 0; j < DD/2; j++) upk2(acc[j], h[2*j], h[2*j+1]);
}

__global__ __launch_bounds__(128) void dpb_kernel(
    const float* __restrict__ w0,  const float* __restrict__ b0_,
    const float* __restrict__ g1,  const float* __restrict__ be1,
    const float* __restrict__ w1,  const float* __restrict__ b1,
    const float* __restrict__ g2,  const float* __restrict__ be2,
    const float* __restrict__ w2,  const float* __restrict__ b2,
    const float* __restrict__ g3,  const float* __restrict__ be3,
    const float* __restrict__ w3,  const float* __restrict__ b3)
{
    __shared__ __align__(16) float sw1[DD*DD], sw2[DD*DD], sw3[DD*HEADS];
    __shared__ __align__(16) float sv[10*DD + HEADS];
    int tid = threadIdx.x;
    for (int i = tid; i < DD*DD; i += 128){ sw1[i] = w1[i]; sw2[i] = w2[i]; }
    for (int i = tid; i < DD*HEADS; i += 128) sw3[i] = w3[i];
    if (tid < 64){
        sv[0*64+tid]=w0[tid];  sv[1*64+tid]=b0_[tid];
        sv[2*64+tid]=g1[tid];  sv[3*64+tid]=be1[tid]; sv[4*64+tid]=b1[tid];
        sv[5*64+tid]=g2[tid];  sv[6*64+tid]=be2[tid]; sv[7*64+tid]=b2[tid];
        sv[8*64+tid]=g3[tid];  sv[9*64+tid]=be3[tid];
        if (tid < HEADS) sv[10*64+tid] = b3[tid];
    }
    __syncthreads();

    int id = blockIdx.x * 128 + tid;     // id = d*8192 + p -> p innermost (coalesced stores)
    int p  = id & (NPOS-1);
    int d  = id >> 13;
    const float scale = 1.0f / (4095.0f * 64.0f);
    float idx;
    if (p == 0 || p == 4096)      idx = 0.0f;
    else if (p < 4096)            idx =  (float)((p-1)*64 + d + 1) * scale;
    else                          idx = -(float)(4095*64 - ((p-4097)*64 + d)) * scale;

    float h[DD];
#pragma unroll
    for (int i = 0; i < DD; i++) h[i] = idx * sv[i] + sv[64+i];

    mlp_layer_p(h, sv+2*64, sv+3*64, sw1, sv+4*64);
    mlp_layer_p(h, sv+5*64, sv+6*64, sw2, sv+7*64);

    float m = 0.f;
#pragma unroll
    for (int i = 0; i < DD; i++) m += h[i];
    m *= (1.f/64.f);
    float v = 0.f;
#pragma unroll
    for (int i = 0; i < DD; i++){ float dd2 = h[i]-m; v += dd2*dd2; }
    v *= (1.f/64.f);
    float rs = rsqrtf(v + 1e-5f);

    u64 o[HEADS/2];
    const u64* b3u = reinterpret_cast<const u64*>(sv + 10*64);
#pragma unroll
    for (int j = 0; j < HEADS/2; j++) o[j] = b3u[j];
    for (int i = 0; i < DD; i++){
        float r = fmaxf((h[i]-m)*rs*sv[8*64+i] + sv[9*64+i], 0.f);
        u64 rp = pk2(r, r);
        const ulonglong2* wr = reinterpret_cast<const ulonglong2*>(sw3 + i*HEADS);
#pragma unroll
        for (int j = 0; j < 4; j++){
            ulonglong2 wv = wr[j];
            o[2*j]   = fma2(rp, wv.x, o[2*j]);
            o[2*j+1] = fma2(rp, wv.y, o[2*j+1]);
        }
    }
#pragma unroll
    for (int j = 0; j < HEADS/2; j++){
        float lo, hi;
        upk2(o[j], lo, hi);
        g_abuf[(size_t)((2*j+0)*64 + d) * NPOS + p] = lo;
        g_abuf[(size_t)((2*j+1)*64 + d) * NPOS + p] = hi;
    }
}

// ------------------------- A spectrum -------------------------
__device__ __forceinline__ void spectralA(const float2* __restrict__ Z, float2* __restrict__ Arow, int k){
    int k2 = 4096 - k;
    float2 Zk = Z[IDX(k)], Zk2 = Z[IDX(k2)];
    float2 E  = make_float2((Zk.x+Zk2.x)*0.5f, (Zk.y-Zk2.y)*0.5f);
    float2 Dm = make_float2((Zk.x-Zk2.x)*0.5f, (Zk.y+Zk2.y)*0.5f);
    float2 O  = make_float2(Dm.y, -Dm.x);                    // -i*Dm
    float sn, cs;
    __sincosf(-7.6699039394282068e-4f * (float)k, &sn, &cs); // -2*pi*k/8192
    float2 TO = cmul(make_float2(cs,sn), O);
    Arow[k]  = make_float2(E.x+TO.x,  E.y+TO.y);
    Arow[k2] = make_float2(E.x-TO.x, -(E.y-TO.y));           // conj(E - T*O)
}

__global__ __launch_bounds__(512) void fft_a_kernel(){
    extern __shared__ float2 sm[];
    float2* b0 = sm;
    float2* b1 = sm + SMEM_ELEMS;
    int t = threadIdx.x;
    int col = blockIdx.x;
    const float2* src = reinterpret_cast<const float2*>(g_abuf + (size_t)col * NPOS);
#pragma unroll
    for (int it = 0; it < 8; it++){
        int k = t + it*512;
        b0[IDX(k)] = src[k];
    }
    __syncthreads();
    run_fft<-1>(b0, b1, t);
    float2* Arow = g_Aspec + (size_t)col * ASTR;
#pragma unroll
    for (int it = 0; it < 4; it++){
        int k = t + it*512;
        if (k == 0){
            float2 Z0 = b0[IDX(0)];
            Arow[0]    = make_float2(Z0.x + Z0.y, 0.f);
            Arow[4096] = make_float2(Z0.x - Z0.y, 0.f);
        } else if (k < 2048) {
            spectralA(b0, Arow, k);
        }
    }
    if (t == 0) spectralA(b0, Arow, 2048);
}

// ------------------------- transposes -------------------------
__global__ __launch_bounds__(256) void transpose_fwd(const float* __restrict__ in){
    __shared__ float tile[32][33];
    int d0 = blockIdx.x*32, n0 = blockIdx.y*32, bh = blockIdx.z;
    const float* src = in + (size_t)bh * SEQ * DIM;
#pragma unroll
    for (int j = 0; j < 4; j++)
        tile[threadIdx.y + 8*j][threadIdx.x] = src[(size_t)(n0 + threadIdx.y + 8*j)*DIM + d0 + threadIdx.x];
    __syncthreads();
    float* dst = g_xt + (size_t)bh * DIM * SEQ;
#pragma unroll
    for (int j = 0; j < 4; j++)
        dst[(size_t)(d0 + threadIdx.y + 8*j)*SEQ + n0 + threadIdx.x] = tile[threadIdx.x][threadIdx.y + 8*j];
}

__global__ __launch_bounds__(256) void transpose_back(float* __restrict__ out){
    __shared__ float tile[32][33];
    int d0 = blockIdx.x*32, n0 = blockIdx.y*32, bh = blockIdx.z;
    const float* src = g_xt + (size_t)bh * DIM * SEQ;
#pragma unroll
    for (int j = 0; j < 4; j++)
        tile[threadIdx.y + 8*j][threadIdx.x] = src[(size_t)(d0 + threadIdx.y + 8*j)*SEQ + n0 + threadIdx.x];
    __syncthreads();
    float* dst = out + (size_t)bh * SEQ * DIM;
#pragma unroll
    for (int j = 0; j < 4; j++)
        dst[(size_t)(n0 + threadIdx.y + 8*j)*DIM + d0 + threadIdx.x] = tile[threadIdx.x][threadIdx.y + 8*j];
}

// ------------------------- x conv -------------------------
__device__ __forceinline__ void spectralX(float2* __restrict__ Z, const float2* __restrict__ Arow, int k){
    int k2 = 4096 - k;
    float2 Zk = Z[IDX(k)], Zk2 = Z[IDX(k2)];
    float2 E  = make_float2((Zk.x+Zk2.x)*0.5f, (Zk.y-Zk2.y)*0.5f);
    float2 Dm = make_float2((Zk.x-Zk2.x)*0.5f, (Zk.y+Zk2.y)*0.5f);
    float2 O  = make_float2(Dm.y, -Dm.x);
    float sn, cs;
    __sincosf(-7.6699039394282068e-4f * (float)k, &sn, &cs);
    float2 T  = make_float2(cs, sn);
    float2 TO = cmul(T, O);
    float2 Y  = make_float2(E.x+TO.x,  E.y+TO.y);
    float2 Y2 = make_float2(E.x-TO.x, -(E.y-TO.y));
    float2 W  = cmul(Y,  Arow[k]);
    float2 W2 = cmul(Y2, Arow[k2]);
    float2 Ep = make_float2((W.x+W2.x)*0.5f, (W.y-W2.y)*0.5f);
    float2 Dp = make_float2((W.x-W2.x)*0.5f, (W.y+W2.y)*0.5f);
    float2 Op = cmul(make_float2(T.x, -T.y), Dp);            // conj(T)*Dp
    Z[IDX(k)]  = make_float2(Ep.x - Op.y,  Ep.y + Op.x);
    Z[IDX(k2)] = make_float2(Ep.x + Op.y, -Ep.y + Op.x);
}

__global__ __launch_bounds__(512) void fft_x_kernel(){
    extern __shared__ float2 sm[];
    float2* b0 = sm;
    float2* b1 = sm + SMEM_ELEMS;
    int t = threadIdx.x;
    int e = blockIdx.x;          // e in [0, 8*1024): b innermost -> 8 CTAs reuse one A row in L2
    int b  = e & 7;
    int hd = e >> 3;             // h*64+d in [0, 1024)
    int h  = hd >> 6;
    int d  = hd & 63;
    int bh = b * HEADS + h;
    float2* col = reinterpret_cast<float2*>(g_xt + ((size_t)bh * DIM + d) * SEQ);

#pragma unroll
    for (int it = 0; it < 4; it++){
        int k = t + it*512;
        b0[IDX(k)]        = col[k];
        b0[IDX(k + 2048)] = make_float2(0.f, 0.f);
    }
    __syncthreads();
    run_fft<-1>(b0, b1, t);

    const float2* Arow = g_Aspec + (size_t)hd * ASTR;
#pragma unroll
    for (int it = 0; it < 4; it++){
        int k = t + it*512;
        if (k == 0){
            float2 Z0 = b0[IDX(0)];
            float Y0 = Z0.x + Z0.y;
            float Y4 = Z0.x - Z0.y;
            float2 A0 = Arow[0], A4 = Arow[4096];
            float W0 = Y0*A0.x;                  // bins 0 & 4096 are purely real
            float W4 = Y4*A4.x;
            b0[IDX(0)] = make_float2((W0+W4)*0.5f, (W0-W4)*0.5f);
        } else if (k < 2048) {
            spectralX(b0, Arow, k);
        }
    }
    if (t == 0) spectralX(b0, Arow, 2048);
    __syncthreads();

    run_fft<1>(b0, b1, t);

    const float inv = 1.f / 4096.f;
#pragma unroll
    for (int it = 0; it < 4; it++){
        int k = t + it*512;
        if (k < 2048){
            float2 z = b0[IDX(k)];
            col[k] = make_float2(z.x * inv, z.y * inv);
        }
    }
}

extern "C" void kernel_launch(void* const* d_in, const int* in_sizes, int n_in,
                              void* d_out, int out_size) {
    (void)in_sizes; (void)n_in; (void)out_size;
    const float* x   = (const float*)d_in[0];
    const float* w0  = (const float*)d_in[1];
    const float* b0_ = (const float*)d_in[2];
    const float* g1  = (const float*)d_in[3];
    const float* be1 = (const float*)d_in[4];
    const float* w1  = (const float*)d_in[5];
    const float* b1  = (const float*)d_in[6];
    const float* g2  = (const float*)d_in[7];
    const float* be2 = (const float*)d_in[8];
    const float* w2  = (const float*)d_in[9];
    const float* b2  = (const float*)d_in[10];
    const float* g3  = (const float*)d_in[11];
    const float* be3 = (const float*)d_in[12];
    const float* w3  = (const float*)d_in[13];
    const float* b3  = (const float*)d_in[14];
    float* out = (float*)d_out;

    static bool attr_done = false;
    if (!attr_done) {
        cudaFuncSetAttribute(fft_a_kernel, cudaFuncAttributeMaxDynamicSharedMemorySize, SMEM_BYTES);
        cudaFuncSetAttribute(fft_x_kernel, cudaFuncAttributeMaxDynamicSharedMemorySize, SMEM_BYTES);
        attr_done = true;
    }

    // 1. MLP -> a coefficients
    dpb_kernel<<<(NPOS*DIM)/128, 128>>>(w0,b0_,g1,be1,w1,b1,g2,be2,w2,b2,g3,be3,w3,b3);
    // 2. A spectrum per (h,d)
    fft_a_kernel<<<NCOLS_A, 512, SMEM_BYTES>>>();
    // 3. transpose x -> [bh][d][n]
    {
        dim3 g(DIM/32, SEQ/32, 128), t(32, 8);
        transpose_fwd<<<g, t>>>(x);
    }
    // 4. FFT conv per column, in place  (8 batches x 1024 (h,d) columns = 8192 CTAs)
    fft_x_kernel<<<8 * NCOLS_A, 512, SMEM_BYTES>>>();
    // 5. transpose back -> out
    {
        dim3 g(DIM/32, SEQ/32, 128), t(32, 8);
        transpose_back<<<g, t>>>(out);
    }
}

// round 6
// speedup vs baseline: 1.1307x; 1.1307x over previous
#include <cuda_runtime.h>
#include <cstdint>

#define SEQ    4096
#define NPOS   8192
#define HEADS  16
#define DIM    64
#define DD     64
#define NCOLS_A 1024
#define ASTR   4104

__device__ float  g_abuf[(size_t)NCOLS_A * NPOS];
__device__ float2 g_Aspec[(size_t)NCOLS_A * ASTR];
__device__ float  g_xt[(size_t)128 * DIM * SEQ];

// XOR swizzle: bijective on [0,4096); makes stride-16 / stride-256 / packed
// accesses all hit the 2-words-per-bank floor for 64-bit LDS/STS.
#define SW(i) ((i) ^ (((i) >> 4) & 0xF))
#define FFT_N 4096
#define SMEM_BYTES (2 * FFT_N * (int)sizeof(float2))

// ---------- packed f32x2 helpers (Blackwell FFMA2 path, PTX-only) ----------
typedef unsigned long long u64;
__device__ __forceinline__ u64 pk2(float lo, float hi){
    u64 r; asm("mov.b64 %0, {%1, %2};" : "=l"(r) : "f"(lo), "f"(hi)); return r;
}
__device__ __forceinline__ void upk2(u64 v, float& lo, float& hi){
    asm("mov.b64 {%0, %1}, %2;" : "=f"(lo), "=f"(hi) : "l"(v));
}
__device__ __forceinline__ u64 fma2(u64 a, u64 b, u64 c){
    u64 d; asm("fma.rn.f32x2 %0, %1, %2, %3;" : "=l"(d) : "l"(a), "l"(b), "l"(c)); return d;
}

__device__ __forceinline__ float2 cadd(float2 a, float2 b){ return make_float2(a.x+b.x, a.y+b.y); }
__device__ __forceinline__ float2 csub(float2 a, float2 b){ return make_float2(a.x-b.x, a.y-b.y); }
__device__ __forceinline__ float2 cmul(float2 a, float2 b){
    return make_float2(a.x*b.x - a.y*b.y, a.x*b.y + a.y*b.x);
}
template<int DIR>
__device__ __forceinline__ float2 mul_i(float2 z){
    return make_float2(-(float)DIR * z.y, (float)DIR * z.x);
}

template<int DIR>
__device__ __forceinline__ void dft4(float2 c0, float2 c1, float2 c2, float2 c3,
                                     float2& d0, float2& d1, float2& d2, float2& d3){
    float2 e0 = cadd(c0,c2), e1 = csub(c0,c2);
    float2 f0 = cadd(c1,c3), f1 = csub(c1,c3);
    float2 t  = mul_i<DIR>(f1);
    d0 = cadd(e0,f0); d2 = csub(e0,f0);
    d1 = cadd(e1,t);  d3 = csub(e1,t);
}

// 16-point DFT: X[k1+4k2] via dft4(n2) -> W16^{n1*k1} -> dft4(n1).
template<int DIR>
__device__ __forceinline__ void dft16(float2 a[16]){
    const float C1 = 0.92387953251128674f, S1 = 0.38268343236508978f;
    const float C2 = 0.70710678118654752f;
    const float D  = (float)DIR;
    float2 g[4][4];
#pragma unroll
    for (int n1 = 0; n1 < 4; n1++)
        dft4<DIR>(a[n1], a[n1+4], a[n1+8], a[n1+12],
                  g[n1][0], g[n1][1], g[n1][2], g[n1][3]);
    // twiddle g[n1][k1] *= W16^{n1*k1},  W16^m = (cos(2pi m/16), DIR*sin(2pi m/16))
    g[1][1] = cmul(g[1][1], make_float2( C1,  D*S1));   // m=1
    g[1][2] = cmul(g[1][2], make_float2( C2,  D*C2));   // m=2
    g[1][3] = cmul(g[1][3], make_float2( S1,  D*C1));   // m=3
    g[2][1] = cmul(g[2][1], make_float2( C2,  D*C2));   // m=2
    g[2][2] = mul_i<DIR>(g[2][2]);                      // m=4
    g[2][3] = cmul(g[2][3], make_float2(-C2,  D*C2));   // m=6
    g[3][1] = cmul(g[3][1], make_float2( S1,  D*C1));   // m=3
    g[3][2] = cmul(g[3][2], make_float2(-C2,  D*C2));   // m=6
    g[3][3] = cmul(g[3][3], make_float2(-C1, -D*S1));   // m=9
#pragma unroll
    for (int k1 = 0; k1 < 4; k1++)
        dft4<DIR>(g[0][k1], g[1][k1], g[2][k1], g[3][k1],
                  a[k1], a[k1+4], a[k1+8], a[k1+12]);
}

// Stockham radix-16 stage: 256 butterflies, thread t does one.
template<int DIR>
__device__ __forceinline__ void fft_stage16(const float2* __restrict__ in, float2* __restrict__ out,
                                            int n, int s, int t){
    int p = t / s;
    int q = t - p * s;
    float2 a[16];
#pragma unroll
    for (int k = 0; k < 16; k++) a[k] = in[SW(t + 256*k)];
    dft16<DIR>(a);
    if (p != 0) {
        float base = (float)DIR * 6.283185307179586f / (float)n;
#pragma unroll
        for (int k = 1; k < 16; k++) {
            int r = (p * k) & (n - 1);
            float sn, cs;
            __sincosf(base * (float)r, &sn, &cs);
            a[k] = cmul(a[k], make_float2(cs, sn));
        }
    }
    int ob = q + s * 16 * p;
#pragma unroll
    for (int k = 0; k < 16; k++) out[SW(ob + s*k)] = a[k];
}

template<int DIR>
__device__ __forceinline__ void run_fft16(float2* b0, float2* b1, int t){
    fft_stage16<DIR>(b0, b1, 4096,   1, t); __syncthreads();
    fft_stage16<DIR>(b1, b0,  256,  16, t); __syncthreads();
    fft_stage16<DIR>(b0, b1,   16, 256, t); __syncthreads();
}
// NOTE: result ends in b1 (3 stages = odd number of ping-pongs).

// ------------------------- dpb MLP (f32x2 packed) -------------------------
__device__ __forceinline__ void mlp_layer_p(float h[DD], const float* __restrict__ g,
                                            const float* __restrict__ be,
                                            const float* __restrict__ w,
                                            const float* __restrict__ b){
    float m = 0.f;
#pragma unroll
    for (int i = 0; i < DD; i++) m += h[i];
    m *= (1.f/64.f);
    float v = 0.f;
#pragma unroll
    for (int i = 0; i < DD; i++){ float d = h[i]-m; v += d*d; }
    v *= (1.f/64.f);
    float rs = rsqrtf(v + 1e-5f);
#pragma unroll
    for (int i = 0; i < DD; i++) h[i] = fmaxf((h[i]-m)*rs*g[i] + be[i], 0.f);

    u64 acc[DD/2];
    const u64* bu = reinterpret_cast<const u64*>(b);
#pragma unroll
    for (int j = 0; j < DD/2; j++) acc[j] = bu[j];
    for (int i = 0; i < DD; i++){
        u64 rp = pk2(h[i], h[i]);
        const ulonglong2* wr = reinterpret_cast<const ulonglong2*>(w + i*DD);
#pragma unroll
        for (int j = 0; j < 16; j++){
            ulonglong2 wv = wr[j];
            acc[2*j]   = fma2(rp, wv.x, acc[2*j]);
            acc[2*j+1] = fma2(rp, wv.y, acc[2*j+1]);
        }
    }
#pragma unroll
    for (int j = 0; j < DD/2; j++) upk2(acc[j], h[2*j], h[2*j+1]);
}

__global__ __launch_bounds__(128) void dpb_kernel(
    const float* __restrict__ w0,  const float* __restrict__ b0_,
    const float* __restrict__ g1,  const float* __restrict__ be1,
    const float* __restrict__ w1,  const float* __restrict__ b1,
    const float* __restrict__ g2,  const float* __restrict__ be2,
    const float* __restrict__ w2,  const float* __restrict__ b2,
    const float* __restrict__ g3,  const float* __restrict__ be3,
    const float* __restrict__ w3,  const float* __restrict__ b3)
{
    __shared__ __align__(16) float sw1[DD*DD], sw2[DD*DD], sw3[DD*HEADS];
    __shared__ __align__(16) float sv[10*DD + HEADS];
    int tid = threadIdx.x;
    for (int i = tid; i < DD*DD; i += 128){ sw1[i] = w1[i]; sw2[i] = w2[i]; }
    for (int i = tid; i < DD*HEADS; i += 128) sw3[i] = w3[i];
    if (tid < 64){
        sv[0*64+tid]=w0[tid];  sv[1*64+tid]=b0_[tid];
        sv[2*64+tid]=g1[tid];  sv[3*64+tid]=be1[tid]; sv[4*64+tid]=b1[tid];
        sv[5*64+tid]=g2[tid];  sv[6*64+tid]=be2[tid]; sv[7*64+tid]=b2[tid];
        sv[8*64+tid]=g3[tid];  sv[9*64+tid]=be3[tid];
        if (tid < HEADS) sv[10*64+tid] = b3[tid];
    }
    __syncthreads();

    int id = blockIdx.x * 128 + tid;     // id = d*8192 + p -> p innermost (coalesced stores)
    int p  = id & (NPOS-1);
    int d  = id >> 13;
    const float scale = 1.0f / (4095.0f * 64.0f);
    float idx;
    if (p == 0 || p == 4096)      idx = 0.0f;
    else if (p < 4096)            idx =  (float)((p-1)*64 + d + 1) * scale;
    else                          idx = -(float)(4095*64 - ((p-4097)*64 + d)) * scale;

    float h[DD];
#pragma unroll
    for (int i = 0; i < DD; i++) h[i] = idx * sv[i] + sv[64+i];

    mlp_layer_p(h, sv+2*64, sv+3*64, sw1, sv+4*64);
    mlp_layer_p(h, sv+5*64, sv+6*64, sw2, sv+7*64);

    float m = 0.f;
#pragma unroll
    for (int i = 0; i < DD; i++) m += h[i];
    m *= (1.f/64.f);
    float v = 0.f;
#pragma unroll
    for (int i = 0; i < DD; i++){ float dd2 = h[i]-m; v += dd2*dd2; }
    v *= (1.f/64.f);
    float rs = rsqrtf(v + 1e-5f);

    u64 o[HEADS/2];
    const u64* b3u = reinterpret_cast<const u64*>(sv + 10*64);
#pragma unroll
    for (int j = 0; j < HEADS/2; j++) o[j] = b3u[j];
    for (int i = 0; i < DD; i++){
        float r = fmaxf((h[i]-m)*rs*sv[8*64+i] + sv[9*64+i], 0.f);
        u64 rp = pk2(r, r);
        const ulonglong2* wr = reinterpret_cast<const ulonglong2*>(sw3 + i*HEADS);
#pragma unroll
        for (int j = 0; j < 4; j++){
            ulonglong2 wv = wr[j];
            o[2*j]   = fma2(rp, wv.x, o[2*j]);
            o[2*j+1] = fma2(rp, wv.y, o[2*j+1]);
        }
    }
#pragma unroll
    for (int j = 0; j < HEADS/2; j++){
        float lo, hi;
        upk2(o[j], lo, hi);
        g_abuf[(size_t)((2*j+0)*64 + d) * NPOS + p] = lo;
        g_abuf[(size_t)((2*j+1)*64 + d) * NPOS + p] = hi;
    }
}

// ------------------------- A spectrum -------------------------
__device__ __forceinline__ void spectralA(const float2* __restrict__ Z, float2* __restrict__ Arow, int k){
    int k2 = 4096 - k;
    float2 Zk = Z[SW(k)], Zk2 = Z[SW(k2)];
    float2 E  = make_float2((Zk.x+Zk2.x)*0.5f, (Zk.y-Zk2.y)*0.5f);
    float2 Dm = make_float2((Zk.x-Zk2.x)*0.5f, (Zk.y+Zk2.y)*0.5f);
    float2 O  = make_float2(Dm.y, -Dm.x);                    // -i*Dm
    float sn, cs;
    __sincosf(-7.6699039394282068e-4f * (float)k, &sn, &cs); // -2*pi*k/8192
    float2 TO = cmul(make_float2(cs,sn), O);
    Arow[k]  = make_float2(E.x+TO.x,  E.y+TO.y);
    Arow[k2] = make_float2(E.x-TO.x, -(E.y-TO.y));           // conj(E - T*O)
}

__global__ __launch_bounds__(256) void fft_a_kernel(){
    extern __shared__ float2 sm[];
    float2* b0 = sm;
    float2* b1 = sm + FFT_N;
    int t = threadIdx.x;
    int col = blockIdx.x;
    const float2* src = reinterpret_cast<const float2*>(g_abuf + (size_t)col * NPOS);
#pragma unroll
    for (int it = 0; it < 16; it++){
        int k = t + it*256;
        b0[SW(k)] = src[k];
    }
    __syncthreads();
    run_fft16<-1>(b0, b1, t);          // result in b1
    float2* Arow = g_Aspec + (size_t)col * ASTR;
#pragma unroll
    for (int it = 0; it < 8; it++){
        int k = t + it*256;
        if (k == 0){
            float2 Z0 = b1[SW(0)];
            Arow[0]    = make_float2(Z0.x + Z0.y, 0.f);
            Arow[4096] = make_float2(Z0.x - Z0.y, 0.f);
        } else if (k < 2048) {
            spectralA(b1, Arow, k);
        }
    }
    if (t == 0) spectralA(b1, Arow, 2048);
}

// ------------------------- transposes -------------------------
__global__ __launch_bounds__(256) void transpose_fwd(const float* __restrict__ in){
    __shared__ float tile[32][33];
    int d0 = blockIdx.x*32, n0 = blockIdx.y*32, bh = blockIdx.z;
    const float* src = in + (size_t)bh * SEQ * DIM;
#pragma unroll
    for (int j = 0; j < 4; j++)
        tile[threadIdx.y + 8*j][threadIdx.x] = src[(size_t)(n0 + threadIdx.y + 8*j)*DIM + d0 + threadIdx.x];
    __syncthreads();
    float* dst = g_xt + (size_t)bh * DIM * SEQ;
#pragma unroll
    for (int j = 0; j < 4; j++)
        dst[(size_t)(d0 + threadIdx.y + 8*j)*SEQ + n0 + threadIdx.x] = tile[threadIdx.x][threadIdx.y + 8*j];
}

__global__ __launch_bounds__(256) void transpose_back(float* __restrict__ out){
    __shared__ float tile[32][33];
    int d0 = blockIdx.x*32, n0 = blockIdx.y*32, bh = blockIdx.z;
    const float* src = g_xt + (size_t)bh * DIM * SEQ;
#pragma unroll
    for (int j = 0; j < 4; j++)
        tile[threadIdx.y + 8*j][threadIdx.x] = src[(size_t)(d0 + threadIdx.y + 8*j)*SEQ + n0 + threadIdx.x];
    __syncthreads();
    float* dst = out + (size_t)bh * SEQ * DIM;
#pragma unroll
    for (int j = 0; j < 4; j++)
        dst[(size_t)(n0 + threadIdx.y + 8*j)*DIM + d0 + threadIdx.x] = tile[threadIdx.x][threadIdx.y + 8*j];
}

// ------------------------- x conv -------------------------
__device__ __forceinline__ void spectralX(float2* __restrict__ Z, const float2* __restrict__ Arow, int k){
    int k2 = 4096 - k;
    float2 Zk = Z[SW(k)], Zk2 = Z[SW(k2)];
    float2 E  = make_float2((Zk.x+Zk2.x)*0.5f, (Zk.y-Zk2.y)*0.5f);
    float2 Dm = make_float2((Zk.x-Zk2.x)*0.5f, (Zk.y+Zk2.y)*0.5f);
    float2 O  = make_float2(Dm.y, -Dm.x);
    float sn, cs;
    __sincosf(-7.6699039394282068e-4f * (float)k, &sn, &cs);
    float2 T  = make_float2(cs, sn);
    float2 TO = cmul(T, O);
    float2 Y  = make_float2(E.x+TO.x,  E.y+TO.y);
    float2 Y2 = make_float2(E.x-TO.x, -(E.y-TO.y));
    float2 W  = cmul(Y,  Arow[k]);
    float2 W2 = cmul(Y2, Arow[k2]);
    float2 Ep = make_float2((W.x+W2.x)*0.5f, (W.y-W2.y)*0.5f);
    float2 Dp = make_float2((W.x-W2.x)*0.5f, (W.y+W2.y)*0.5f);
    float2 Op = cmul(make_float2(T.x, -T.y), Dp);            // conj(T)*Dp
    Z[SW(k)]  = make_float2(Ep.x - Op.y,  Ep.y + Op.x);
    Z[SW(k2)] = make_float2(Ep.x + Op.y, -Ep.y + Op.x);
}

__global__ __launch_bounds__(256) void fft_x_kernel(){
    extern __shared__ float2 sm[];
    float2* b0 = sm;
    float2* b1 = sm + FFT_N;
    int t = threadIdx.x;
    int e = blockIdx.x;          // e in [0, 8*1024): b innermost -> 8 CTAs reuse one A row in L2
    int b  = e & 7;
    int hd = e >> 3;             // h*64+d in [0, 1024)
    int h  = hd >> 6;
    int d  = hd & 63;
    int bh = b * HEADS + h;
    float2* col = reinterpret_cast<float2*>(g_xt + ((size_t)bh * DIM + d) * SEQ);

#pragma unroll
    for (int it = 0; it < 8; it++){
        int k = t + it*256;
        b0[SW(k)]        = col[k];
        b0[SW(k + 2048)] = make_float2(0.f, 0.f);
    }
    __syncthreads();
    run_fft16<-1>(b0, b1, t);        // forward result in b1

    const float2* Arow = g_Aspec + (size_t)hd * ASTR;
#pragma unroll
    for (int it = 0; it < 8; it++){
        int k = t + it*256;
        if (k == 0){
            float2 Z0 = b1[SW(0)];
            float Y0 = Z0.x + Z0.y;
            float Y4 = Z0.x - Z0.y;
            float2 A0 = Arow[0], A4 = Arow[4096];
            float W0 = Y0*A0.x;                  // bins 0 & 4096 are purely real
            float W4 = Y4*A4.x;
            b1[SW(0)] = make_float2((W0+W4)*0.5f, (W0-W4)*0.5f);
        } else if (k < 2048) {
            spectralX(b1, Arow, k);
        }
    }
    if (t == 0) spectralX(b1, Arow, 2048);
    __syncthreads();

    run_fft16<1>(b1, b0, t);         // inverse: input b1, result in b0

    const float inv = 1.f / 4096.f;
#pragma unroll
    for (int it = 0; it < 8; it++){
        int k = t + it*256;
        if (k < 2048){
            float2 z = b0[SW(k)];
            col[k] = make_float2(z.x * inv, z.y * inv);
        }
    }
}

extern "C" void kernel_launch(void* const* d_in, const int* in_sizes, int n_in,
                              void* d_out, int out_size) {
    (void)in_sizes; (void)n_in; (void)out_size;
    const float* x   = (const float*)d_in[0];
    const float* w0  = (const float*)d_in[1];
    const float* b0_ = (const float*)d_in[2];
    const float* g1  = (const float*)d_in[3];
    const float* be1 = (const float*)d_in[4];
    const float* w1  = (const float*)d_in[5];
    const float* b1  = (const float*)d_in[6];
    const float* g2  = (const float*)d_in[7];
    const float* be2 = (const float*)d_in[8];
    const float* w2  = (const float*)d_in[9];
    const float* b2  = (const float*)d_in[10];
    const float* g3  = (const float*)d_in[11];
    const float* be3 = (const float*)d_in[12];
    const float* w3  = (const float*)d_in[13];
    const float* b3  = (const float*)d_in[14];
    float* out = (float*)d_out;

    static bool attr_done = false;
    if (!attr_done) {
        cudaFuncSetAttribute(fft_a_kernel, cudaFuncAttributeMaxDynamicSharedMemorySize, SMEM_BYTES);
        cudaFuncSetAttribute(fft_x_kernel, cudaFuncAttributeMaxDynamicSharedMemorySize, SMEM_BYTES);
        attr_done = true;
    }

    // 1. MLP -> a coefficients
    dpb_kernel<<<(NPOS*DIM)/128, 128>>>(w0,b0_,g1,be1,w1,b1,g2,be2,w2,b2,g3,be3,w3,b3);
    // 2. A spectrum per (h,d)
    fft_a_kernel<<<NCOLS_A, 256, SMEM_BYTES>>>();
    // 3. transpose x -> [bh][d][n]
    {
        dim3 g(DIM/32, SEQ/32, 128), t(32, 8);
        transpose_fwd<<<g, t>>>(x);
    }
    // 4. FFT conv per column, in place  (8 batches x 1024 (h,d) columns = 8192 CTAs)
    fft_x_kernel<<<8 * NCOLS_A, 256, SMEM_BYTES>>>();
    // 5. transpose back -> out
    {
        dim3 g(DIM/32, SEQ/32, 128), t(32, 8);
        transpose_back<<<g, t>>>(out);
    }
}

// round 7
// speedup vs baseline: 1.1783x; 1.0421x over previous
#include <cuda_runtime.h>
#include <cstdint>

#define SEQ    4096
#define NPOS   8192
#define HEADS  16
#define DIM    64
#define DD     64
#define NCOLS_A 1024
#define ASTR   4104

__device__ float  g_abuf[(size_t)NCOLS_A * NPOS];
__device__ float2 g_Aspec[(size_t)NCOLS_A * ASTR];
__device__ float  g_xt[(size_t)128 * DIM * SEQ];

// XOR swizzle: bijective on [0,4096); stride-16/256 and packed accesses all
// hit the 2-words-per-bank floor for 64-bit LDS/STS.
#define SW(i) ((i) ^ (((i) >> 4) & 0xF))
#define FFT_N 4096
#define SMEM_BYTES (2 * FFT_N * (int)sizeof(float2))

// ---------- packed f32x2 helpers (Blackwell FFMA2 path, PTX-only) ----------
typedef unsigned long long u64;
__device__ __forceinline__ u64 pk2(float lo, float hi){
    u64 r; asm("mov.b64 %0, {%1, %2};" : "=l"(r) : "f"(lo), "f"(hi)); return r;
}
__device__ __forceinline__ void upk2(u64 v, float& lo, float& hi){
    asm("mov.b64 {%0, %1}, %2;" : "=f"(lo), "=f"(hi) : "l"(v));
}
__device__ __forceinline__ u64 fma2(u64 a, u64 b, u64 c){
    u64 d; asm("fma.rn.f32x2 %0, %1, %2, %3;" : "=l"(d) : "l"(a), "l"(b), "l"(c)); return d;
}

__device__ __forceinline__ float2 cadd(float2 a, float2 b){ return make_float2(a.x+b.x, a.y+b.y); }
__device__ __forceinline__ float2 csub(float2 a, float2 b){ return make_float2(a.x-b.x, a.y-b.y); }
__device__ __forceinline__ float2 cmul(float2 a, float2 b){
    return make_float2(a.x*b.x - a.y*b.y, a.x*b.y + a.y*b.x);
}
template<int DIR>
__device__ __forceinline__ float2 mul_i(float2 z){
    return make_float2(-(float)DIR * z.y, (float)DIR * z.x);
}

template<int DIR>
__device__ __forceinline__ void dft4(float2 c0, float2 c1, float2 c2, float2 c3,
                                     float2& d0, float2& d1, float2& d2, float2& d3){
    float2 e0 = cadd(c0,c2), e1 = csub(c0,c2);
    float2 f0 = cadd(c1,c3), f1 = csub(c1,c3);
    float2 t  = mul_i<DIR>(f1);
    d0 = cadd(e0,f0); d2 = csub(e0,f0);
    d1 = cadd(e1,t);  d3 = csub(e1,t);
}

// shared tail of the 16-pt DFT: twiddle g[n1][k1] by W16^{n1*k1}, then 4 dft4s.
template<int DIR>
__device__ __forceinline__ void dft16_tail(float2 g[4][4], float2 a[16]){
    const float C1 = 0.92387953251128674f, S1 = 0.38268343236508978f;
    const float C2 = 0.70710678118654752f;
    const float D  = (float)DIR;
    g[1][1] = cmul(g[1][1], make_float2( C1,  D*S1));   // m=1
    g[1][2] = cmul(g[1][2], make_float2( C2,  D*C2));   // m=2
    g[1][3] = cmul(g[1][3], make_float2( S1,  D*C1));   // m=3
    g[2][1] = cmul(g[2][1], make_float2( C2,  D*C2));   // m=2
    g[2][2] = mul_i<DIR>(g[2][2]);                      // m=4
    g[2][3] = cmul(g[2][3], make_float2(-C2,  D*C2));   // m=6
    g[3][1] = cmul(g[3][1], make_float2( S1,  D*C1));   // m=3
    g[3][2] = cmul(g[3][2], make_float2(-C2,  D*C2));   // m=6
    g[3][3] = cmul(g[3][3], make_float2(-C1, -D*S1));   // m=9
#pragma unroll
    for (int k1 = 0; k1 < 4; k1++)
        dft4<DIR>(g[0][k1], g[1][k1], g[2][k1], g[3][k1],
                  a[k1], a[k1+4], a[k1+8], a[k1+12]);
}

template<int DIR>
__device__ __forceinline__ void dft16(float2 a[16]){
    float2 g[4][4];
#pragma unroll
    for (int n1 = 0; n1 < 4; n1++)
        dft4<DIR>(a[n1], a[n1+4], a[n1+8], a[n1+12],
                  g[n1][0], g[n1][1], g[n1][2], g[n1][3]);
    dft16_tail<DIR>(g, a);
}

// 16-pt DFT with inputs a[8..15] == 0 (zero-padded tail); only a[0..7] read.
template<int DIR>
__device__ __forceinline__ void dft16_half(float2 a[16]){
    float2 g[4][4];
#pragma unroll
    for (int n1 = 0; n1 < 4; n1++){
        float2 x = a[n1], y = a[n1+4];
        float2 iy = mul_i<DIR>(y);
        g[n1][0] = cadd(x, y);
        g[n1][1] = cadd(x, iy);
        g[n1][2] = csub(x, y);
        g[n1][3] = csub(x, iy);
    }
    dft16_tail<DIR>(g, a);
}

// twiddle a[k] *= W_n^{p*k} via one sincos + chained cmul (no MUFU per k).
template<int DIR>
__device__ __forceinline__ void twiddle16(float2 a[16], int p, int n){
    if (p != 0){
        float ang = (float)DIR * 6.283185307179586f * (float)p / (float)n;
        float sn, cs;
        __sincosf(ang, &sn, &cs);
        float2 w = make_float2(cs, sn), tw = w;
        a[1] = cmul(a[1], tw);
#pragma unroll
        for (int k = 2; k < 16; k++){ tw = cmul(tw, w); a[k] = cmul(a[k], tw); }
    }
}

// Stockham radix-16 stage: 256 butterflies, thread t does one.
template<int DIR>
__device__ __forceinline__ void fft_stage16(const float2* __restrict__ in, float2* __restrict__ out,
                                            int n, int s, int t){
    int p = t / s;
    int q = t - p * s;
    float2 a[16];
#pragma unroll
    for (int k = 0; k < 16; k++) a[k] = in[SW(t + 256*k)];
    dft16<DIR>(a);
    twiddle16<DIR>(a, p, n);
    int ob = q + s * 16 * p;
#pragma unroll
    for (int k = 0; k < 16; k++) out[SW(ob + s*k)] = a[k];
}

template<int DIR>
__device__ __forceinline__ void run_fft16(float2* b0, float2* b1, int t){
    fft_stage16<DIR>(b0, b1, 4096,   1, t); __syncthreads();
    fft_stage16<DIR>(b1, b0,  256,  16, t); __syncthreads();
    fft_stage16<DIR>(b0, b1,   16, 256, t); __syncthreads();
}
// result ends in b1 (odd number of ping-pongs)

// ------------------------- dpb MLP (f32x2 packed) -------------------------
__device__ __forceinline__ void mlp_layer_p(float h[DD], const float* __restrict__ g,
                                            const float* __restrict__ be,
                                            const float* __restrict__ w,
                                            const float* __restrict__ b){
    float m = 0.f;
#pragma unroll
    for (int i = 0; i < DD; i++) m += h[i];
    m *= (1.f/64.f);
    float v = 0.f;
#pragma unroll
    for (int i = 0; i < DD; i++){ float d = h[i]-m; v += d*d; }
    v *= (1.f/64.f);
    float rs = rsqrtf(v + 1e-5f);
#pragma unroll
    for (int i = 0; i < DD; i++) h[i] = fmaxf((h[i]-m)*rs*g[i] + be[i], 0.f);

    u64 acc[DD/2];
    const u64* bu = reinterpret_cast<const u64*>(b);
#pragma unroll
    for (int j = 0; j < DD/2; j++) acc[j] = bu[j];
    for (int i = 0; i < DD; i++){
        u64 rp = pk2(h[i], h[i]);
        const ulonglong2* wr = reinterpret_cast<const ulonglong2*>(w + i*DD);
#pragma unroll
        for (int j = 0; j < 16; j++){
            ulonglong2 wv = wr[j];
            acc[2*j]   = fma2(rp, wv.x, acc[2*j]);
            acc[2*j+1] = fma2(rp, wv.y, acc[2*j+1]);
        }
    }
#pragma unroll
    for (int j = 0; j < DD/2; j++) upk2(acc[j], h[2*j], h[2*j+1]);
}

__global__ __launch_bounds__(128) void dpb_kernel(
    const float* __restrict__ w0,  const float* __restrict__ b0_,
    const float* __restrict__ g1,  const float* __restrict__ be1,
    const float* __restrict__ w1,  const float* __restrict__ b1,
    const float* __restrict__ g2,  const float* __restrict__ be2,
    const float* __restrict__ w2,  const float* __restrict__ b2,
    const float* __restrict__ g3,  const float* __restrict__ be3,
    const float* __restrict__ w3,  const float* __restrict__ b3)
{
    __shared__ __align__(16) float sw1[DD*DD], sw2[DD*DD], sw3[DD*HEADS];
    __shared__ __align__(16) float sv[10*DD + HEADS];
    int tid = threadIdx.x;
    for (int i = tid; i < DD*DD; i += 128){ sw1[i] = w1[i]; sw2[i] = w2[i]; }
    for (int i = tid; i < DD*HEADS; i += 128) sw3[i] = w3[i];
    if (tid < 64){
        sv[0*64+tid]=w0[tid];  sv[1*64+tid]=b0_[tid];
        sv[2*64+tid]=g1[tid];  sv[3*64+tid]=be1[tid]; sv[4*64+tid]=b1[tid];
        sv[5*64+tid]=g2[tid];  sv[6*64+tid]=be2[tid]; sv[7*64+tid]=b2[tid];
        sv[8*64+tid]=g3[tid];  sv[9*64+tid]=be3[tid];
        if (tid < HEADS) sv[10*64+tid] = b3[tid];
    }
    __syncthreads();

    int id = blockIdx.x * 128 + tid;     // id = d*8192 + p -> p innermost (coalesced stores)
    int p  = id & (NPOS-1);
    int d  = id >> 13;
    const float scale = 1.0f / (4095.0f * 64.0f);
    float idx;
    if (p == 0 || p == 4096)      idx = 0.0f;
    else if (p < 4096)            idx =  (float)((p-1)*64 + d + 1) * scale;
    else                          idx = -(float)(4095*64 - ((p-4097)*64 + d)) * scale;

    float h[DD];
#pragma unroll
    for (int i = 0; i < DD; i++) h[i] = idx * sv[i] + sv[64+i];

    mlp_layer_p(h, sv+2*64, sv+3*64, sw1, sv+4*64);
    mlp_layer_p(h, sv+5*64, sv+6*64, sw2, sv+7*64);

    float m = 0.f;
#pragma unroll
    for (int i = 0; i < DD; i++) m += h[i];
    m *= (1.f/64.f);
    float v = 0.f;
#pragma unroll
    for (int i = 0; i < DD; i++){ float dd2 = h[i]-m; v += dd2*dd2; }
    v *= (1.f/64.f);
    float rs = rsqrtf(v + 1e-5f);

    u64 o[HEADS/2];
    const u64* b3u = reinterpret_cast<const u64*>(sv + 10*64);
#pragma unroll
    for (int j = 0; j < HEADS/2; j++) o[j] = b3u[j];
    for (int i = 0; i < DD; i++){
        float r = fmaxf((h[i]-m)*rs*sv[8*64+i] + sv[9*64+i], 0.f);
        u64 rp = pk2(r, r);
        const ulonglong2* wr = reinterpret_cast<const ulonglong2*>(sw3 + i*HEADS);
#pragma unroll
        for (int j = 0; j < 4; j++){
            ulonglong2 wv = wr[j];
            o[2*j]   = fma2(rp, wv.x, o[2*j]);
            o[2*j+1] = fma2(rp, wv.y, o[2*j+1]);
        }
    }
#pragma unroll
    for (int j = 0; j < HEADS/2; j++){
        float lo, hi;
        upk2(o[j], lo, hi);
        g_abuf[(size_t)((2*j+0)*64 + d) * NPOS + p] = lo;
        g_abuf[(size_t)((2*j+1)*64 + d) * NPOS + p] = hi;
    }
}

// ------------------------- A spectrum -------------------------
// T = e^{-2*pi*i*k/8192} precomputed by caller (chained, no per-k sincos).
__device__ __forceinline__ void spectralA(const float2* __restrict__ Z, float2* __restrict__ Arow,
                                          int k, float2 T){
    int k2 = 4096 - k;
    float2 Zk = Z[SW(k)], Zk2 = Z[SW(k2)];
    float2 E  = make_float2((Zk.x+Zk2.x)*0.5f, (Zk.y-Zk2.y)*0.5f);
    float2 Dm = make_float2((Zk.x-Zk2.x)*0.5f, (Zk.y+Zk2.y)*0.5f);
    float2 O  = make_float2(Dm.y, -Dm.x);                    // -i*Dm
    float2 TO = cmul(T, O);
    Arow[k]  = make_float2(E.x+TO.x,  E.y+TO.y);
    Arow[k2] = make_float2(E.x-TO.x, -(E.y-TO.y));           // conj(E - T*O)
}

// chain step: e^{-i*pi/16} (Delta k = 256 between iterations)
#define DLT make_float2(0.98078528040323044f, -0.19509032201612827f)

__global__ __launch_bounds__(256) void fft_a_kernel(){
    extern __shared__ float2 sm[];
    float2* b0 = sm;
    float2* b1 = sm + FFT_N;
    int t = threadIdx.x;
    int col = blockIdx.x;
    const float2* src = reinterpret_cast<const float2*>(g_abuf + (size_t)col * NPOS);
#pragma unroll
    for (int it = 0; it < 16; it++){
        int k = t + it*256;
        b0[SW(k)] = src[k];
    }
    __syncthreads();
    run_fft16<-1>(b0, b1, t);          // result in b1
    float2* Arow = g_Aspec + (size_t)col * ASTR;

    float sn, cs;
    __sincosf(-7.6699039394282068e-4f * (float)t, &sn, &cs); // -2*pi*t/8192
    float2 T = make_float2(cs, sn);
#pragma unroll
    for (int it = 0; it < 8; it++){
        int k = t + it*256;
        if (k == 0){
            float2 Z0 = b1[SW(0)];
            Arow[0]    = make_float2(Z0.x + Z0.y, 0.f);
            Arow[4096] = make_float2(Z0.x - Z0.y, 0.f);
        } else {
            spectralA(b1, Arow, k, T);
        }
        T = cmul(T, DLT);
    }
    if (t == 0) spectralA(b1, Arow, 2048, make_float2(0.f, -1.f));
}

// ------------------------- transposes -------------------------
__global__ __launch_bounds__(256) void transpose_fwd(const float* __restrict__ in){
    __shared__ float tile[32][33];
    int d0 = blockIdx.x*32, n0 = blockIdx.y*32, bh = blockIdx.z;
    const float* src = in + (size_t)bh * SEQ * DIM;
#pragma unroll
    for (int j = 0; j < 4; j++)
        tile[threadIdx.y + 8*j][threadIdx.x] = src[(size_t)(n0 + threadIdx.y + 8*j)*DIM + d0 + threadIdx.x];
    __syncthreads();
    float* dst = g_xt + (size_t)bh * DIM * SEQ;
#pragma unroll
    for (int j = 0; j < 4; j++)
        dst[(size_t)(d0 + threadIdx.y + 8*j)*SEQ + n0 + threadIdx.x] = tile[threadIdx.x][threadIdx.y + 8*j];
}

__global__ __launch_bounds__(256) void transpose_back(float* __restrict__ out){
    __shared__ float tile[32][33];
    int d0 = blockIdx.x*32, n0 = blockIdx.y*32, bh = blockIdx.z;
    const float* src = g_xt + (size_t)bh * DIM * SEQ;
#pragma unroll
    for (int j = 0; j < 4; j++)
        tile[threadIdx.y + 8*j][threadIdx.x] = src[(size_t)(d0 + threadIdx.y + 8*j)*SEQ + n0 + threadIdx.x];
    __syncthreads();
    float* dst = out + (size_t)bh * SEQ * DIM;
#pragma unroll
    for (int j = 0; j < 4; j++)
        dst[(size_t)(n0 + threadIdx.y + 8*j)*DIM + d0 + threadIdx.x] = tile[threadIdx.x][threadIdx.y + 8*j];
}

// ------------------------- x conv -------------------------
__device__ __forceinline__ void spectralX(float2* __restrict__ Z, const float2* __restrict__ Arow,
                                          int k, float2 T){
    int k2 = 4096 - k;
    float2 Zk = Z[SW(k)], Zk2 = Z[SW(k2)];
    float2 E  = make_float2((Zk.x+Zk2.x)*0.5f, (Zk.y-Zk2.y)*0.5f);
    float2 Dm = make_float2((Zk.x-Zk2.x)*0.5f, (Zk.y+Zk2.y)*0.5f);
    float2 O  = make_float2(Dm.y, -Dm.x);
    float2 TO = cmul(T, O);
    float2 Y  = make_float2(E.x+TO.x,  E.y+TO.y);
    float2 Y2 = make_float2(E.x-TO.x, -(E.y-TO.y));
    float2 W  = cmul(Y,  Arow[k]);
    float2 W2 = cmul(Y2, Arow[k2]);
    float2 Ep = make_float2((W.x+W2.x)*0.5f, (W.y-W2.y)*0.5f);
    float2 Dp = make_float2((W.x-W2.x)*0.5f, (W.y+W2.y)*0.5f);
    float2 Op = cmul(make_float2(T.x, -T.y), Dp);            // conj(T)*Dp
    Z[SW(k)]  = make_float2(Ep.x - Op.y,  Ep.y + Op.x);
    Z[SW(k2)] = make_float2(Ep.x + Op.y, -Ep.y + Op.x);
}

__global__ __launch_bounds__(256) void fft_x_kernel(){
    extern __shared__ float2 sm[];
    float2* b0 = sm;
    float2* b1 = sm + FFT_N;
    int t = threadIdx.x;
    int e = blockIdx.x;          // b innermost -> 8 CTAs reuse one A row in L2
    int b  = e & 7;
    int hd = e >> 3;
    int h  = hd >> 6;
    int d  = hd & 63;
    int bh = b * HEADS + h;
    float2* col = reinterpret_cast<float2*>(g_xt + ((size_t)bh * DIM + d) * SEQ);

    // forward stage 1 (n=4096, s=1): inputs k>=8 are the zero pad -> load
    // 8 coalesced float2 straight from gmem, half-zero dft16, store to b0.
    {
        float2 a[16];
#pragma unroll
        for (int k = 0; k < 8; k++) a[k] = col[t + 256*k];
        dft16_half<-1>(a);
        twiddle16<-1>(a, t, 4096);
#pragma unroll
        for (int k = 0; k < 16; k++) b0[SW(16*t + k)] = a[k];
    }
    __syncthreads();
    fft_stage16<-1>(b0, b1, 256,  16, t); __syncthreads();
    fft_stage16<-1>(b1, b0,  16, 256, t); __syncthreads();   // fwd result in b0

    // spectral multiply, in place on b0 (each (k, 4096-k) pair owned by one thread)
    const float2* Arow = g_Aspec + (size_t)hd * ASTR;
    {
        float sn, cs;
        __sincosf(-7.6699039394282068e-4f * (float)t, &sn, &cs);
        float2 T = make_float2(cs, sn);
#pragma unroll
        for (int it = 0; it < 8; it++){
            int k = t + it*256;
            if (k == 0){
                float2 Z0 = b0[SW(0)];
                float Y0 = Z0.x + Z0.y;
                float Y4 = Z0.x - Z0.y;
                float W0 = Y0*Arow[0].x;             // bins 0 & 4096 purely real
                float W4 = Y4*Arow[4096].x;
                b0[SW(0)] = make_float2((W0+W4)*0.5f, (W0-W4)*0.5f);
            } else {
                spectralX(b0, Arow, k, T);
            }
            T = cmul(T, DLT);
        }
        if (t == 0) spectralX(b0, Arow, 2048, make_float2(0.f, -1.f));
    }
    __syncthreads();

    // inverse: stages 1,2 in smem; stage 3 (n=16, s=256 -> p=0, no twiddle,
    // only outputs k<8 are kept) computes in regs and stores straight to gmem.
    fft_stage16<1>(b0, b1, 4096,  1, t); __syncthreads();
    fft_stage16<1>(b1, b0,  256, 16, t); __syncthreads();
    {
        float2 a[16];
#pragma unroll
        for (int k = 0; k < 16; k++) a[k] = b0[SW(t + 256*k)];
        dft16<1>(a);
        const float inv = 1.f / 4096.f;
#pragma unroll
        for (int k = 0; k < 8; k++)
            col[t + 256*k] = make_float2(a[k].x * inv, a[k].y * inv);
    }
}

extern "C" void kernel_launch(void* const* d_in, const int* in_sizes, int n_in,
                              void* d_out, int out_size) {
    (void)in_sizes; (void)n_in; (void)out_size;
    const float* x   = (const float*)d_in[0];
    const float* w0  = (const float*)d_in[1];
    const float* b0_ = (const float*)d_in[2];
    const float* g1  = (const float*)d_in[3];
    const float* be1 = (const float*)d_in[4];
    const float* w1  = (const float*)d_in[5];
    const float* b1  = (const float*)d_in[6];
    const float* g2  = (const float*)d_in[7];
    const float* be2 = (const float*)d_in[8];
    const float* w2  = (const float*)d_in[9];
    const float* b2  = (const float*)d_in[10];
    const float* g3  = (const float*)d_in[11];
    const float* be3 = (const float*)d_in[12];
    const float* w3  = (const float*)d_in[13];
    const float* b3  = (const float*)d_in[14];
    float* out = (float*)d_out;

    static bool attr_done = false;
    if (!attr_done) {
        cudaFuncSetAttribute(fft_a_kernel, cudaFuncAttributeMaxDynamicSharedMemorySize, SMEM_BYTES);
        cudaFuncSetAttribute(fft_x_kernel, cudaFuncAttributeMaxDynamicSharedMemorySize, SMEM_BYTES);
        attr_done = true;
    }

    // 1. MLP -> a coefficients
    dpb_kernel<<<(NPOS*DIM)/128, 128>>>(w0,b0_,g1,be1,w1,b1,g2,be2,w2,b2,g3,be3,w3,b3);
    // 2. A spectrum per (h,d)
    fft_a_kernel<<<NCOLS_A, 256, SMEM_BYTES>>>();
    // 3. transpose x -> [bh][d][n]
    {
        dim3 g(DIM/32, SEQ/32, 128), t(32, 8);
        transpose_fwd<<<g, t>>>(x);
    }
    // 4. FFT conv per column, in place  (8 batches x 1024 (h,d) columns)
    fft_x_kernel<<<8 * NCOLS_A, 256, SMEM_BYTES>>>();
    // 5. transpose back -> out
    {
        dim3 g(DIM/32, SEQ/32, 128), t(32, 8);
        transpose_back<<<g, t>>>(out);
    }
}

// round 8
// speedup vs baseline: 1.3337x; 1.1319x over previous
#include <cuda_runtime.h>
#include <cstdint>

#define SEQ    4096
#define NPOS   8192
#define HEADS  16
#define DIM    64
#define DD     64
#define NCOLS_A 1024
#define ASTR   4104

__device__ float  g_abuf[(size_t)NCOLS_A * NPOS];
__device__ float2 g_Aspec[(size_t)NCOLS_A * ASTR];
__device__ float  g_xt[(size_t)128 * DIM * SEQ];

// XOR swizzle: bijective on [0,4096); stride-16/256 and packed accesses all
// hit the 2-words-per-bank floor for 64-bit LDS/STS.
#define SW(i) ((i) ^ (((i) >> 4) & 0xF))
#define FFT_N 4096
#define FFT_SMEM_BYTES (FFT_N * (int)sizeof(float2))   // single buffer: 32 KB

// ---------- packed f32x2 helpers ----------
typedef unsigned long long u64;
__device__ __forceinline__ u64 pk2(float lo, float hi){
    u64 r; asm("mov.b64 %0, {%1, %2};" : "=l"(r) : "f"(lo), "f"(hi)); return r;
}
__device__ __forceinline__ void upk2(u64 v, float& lo, float& hi){
    asm("mov.b64 {%0, %1}, %2;" : "=f"(lo), "=f"(hi) : "l"(v));
}
__device__ __forceinline__ u64 fma2(u64 a, u64 b, u64 c){
    u64 d; asm("fma.rn.f32x2 %0, %1, %2, %3;" : "=l"(d) : "l"(a), "l"(b), "l"(c)); return d;
}

__device__ __forceinline__ float2 cadd(float2 a, float2 b){ return make_float2(a.x+b.x, a.y+b.y); }
__device__ __forceinline__ float2 csub(float2 a, float2 b){ return make_float2(a.x-b.x, a.y-b.y); }
__device__ __forceinline__ float2 cmul(float2 a, float2 b){
    return make_float2(a.x*b.x - a.y*b.y, a.x*b.y + a.y*b.x);
}
template<int DIR>
__device__ __forceinline__ float2 mul_i(float2 z){
    return make_float2(-(float)DIR * z.y, (float)DIR * z.x);
}

template<int DIR>
__device__ __forceinline__ void dft4(float2 c0, float2 c1, float2 c2, float2 c3,
                                     float2& d0, float2& d1, float2& d2, float2& d3){
    float2 e0 = cadd(c0,c2), e1 = csub(c0,c2);
    float2 f0 = cadd(c1,c3), f1 = csub(c1,c3);
    float2 t  = mul_i<DIR>(f1);
    d0 = cadd(e0,f0); d2 = csub(e0,f0);
    d1 = cadd(e1,t);  d3 = csub(e1,t);
}

template<int DIR>
__device__ __forceinline__ void dft16_tail(float2 g[4][4], float2 a[16]){
    const float C1 = 0.92387953251128674f, S1 = 0.38268343236508978f;
    const float C2 = 0.70710678118654752f;
    const float D  = (float)DIR;
    g[1][1] = cmul(g[1][1], make_float2( C1,  D*S1));
    g[1][2] = cmul(g[1][2], make_float2( C2,  D*C2));
    g[1][3] = cmul(g[1][3], make_float2( S1,  D*C1));
    g[2][1] = cmul(g[2][1], make_float2( C2,  D*C2));
    g[2][2] = mul_i<DIR>(g[2][2]);
    g[2][3] = cmul(g[2][3], make_float2(-C2,  D*C2));
    g[3][1] = cmul(g[3][1], make_float2( S1,  D*C1));
    g[3][2] = cmul(g[3][2], make_float2(-C2,  D*C2));
    g[3][3] = cmul(g[3][3], make_float2(-C1, -D*S1));
#pragma unroll
    for (int k1 = 0; k1 < 4; k1++)
        dft4<DIR>(g[0][k1], g[1][k1], g[2][k1], g[3][k1],
                  a[k1], a[k1+4], a[k1+8], a[k1+12]);
}

template<int DIR>
__device__ __forceinline__ void dft16(float2 a[16]){
    float2 g[4][4];
#pragma unroll
    for (int n1 = 0; n1 < 4; n1++)
        dft4<DIR>(a[n1], a[n1+4], a[n1+8], a[n1+12],
                  g[n1][0], g[n1][1], g[n1][2], g[n1][3]);
    dft16_tail<DIR>(g, a);
}

// 16-pt DFT with inputs a[8..15] == 0.
template<int DIR>
__device__ __forceinline__ void dft16_half(float2 a[16]){
    float2 g[4][4];
#pragma unroll
    for (int n1 = 0; n1 < 4; n1++){
        float2 x = a[n1], y = a[n1+4];
        float2 iy = mul_i<DIR>(y);
        g[n1][0] = cadd(x, y);
        g[n1][1] = cadd(x, iy);
        g[n1][2] = csub(x, y);
        g[n1][3] = csub(x, iy);
    }
    dft16_tail<DIR>(g, a);
}

// twiddle a[k] *= W_n^{p*k}: one sincos + chained cmul.
template<int DIR>
__device__ __forceinline__ void twiddle16(float2 a[16], int p, int n){
    if (p != 0){
        float ang = (float)DIR * 6.283185307179586f * (float)p / (float)n;
        float sn, cs;
        __sincosf(ang, &sn, &cs);
        float2 w = make_float2(cs, sn), tw = w;
        a[1] = cmul(a[1], tw);
#pragma unroll
        for (int k = 2; k < 16; k++){ tw = cmul(tw, w); a[k] = cmul(a[k], tw); }
    }
}

// Single-buffer Stockham radix-16 stage: read-all -> sync -> write-all -> sync.
template<int DIR>
__device__ __forceinline__ void fft_stage16_sb(float2* buf, int n, int s, int t){
    int p = t / s;
    int q = t - p * s;
    float2 a[16];
#pragma unroll
    for (int k = 0; k < 16; k++) a[k] = buf[SW(t + 256*k)];
    dft16<DIR>(a);
    twiddle16<DIR>(a, p, n);
    __syncthreads();
    int ob = q + s * 16 * p;
#pragma unroll
    for (int k = 0; k < 16; k++) buf[SW(ob + s*k)] = a[k];
    __syncthreads();
}

// ------------------------- dpb MLP v2: smem-tiled GEMM -------------------------
// CTA: 128 threads, 128 positions. act/r buffers [64][SACT] (i-major).
#define SACT 130
#define OFF_SW1 0
#define OFF_SW2 4096
#define OFF_SW3 8192
#define OFF_SV  9216
#define OFF_ACT 9872
#define OFF_R   (OFF_ACT + 64*SACT)
#define DPB_SMEM_BYTES ((OFF_R + 64*SACT) * 4)

// LN + relu: thread tid owns position p=tid; reads act column, writes r column.
__device__ __forceinline__ void dpb_ln(const float* __restrict__ act, float* __restrict__ r,
                                       const float* __restrict__ g, const float* __restrict__ be,
                                       int p){
    float h[64];
    float s = 0.f;
#pragma unroll
    for (int i = 0; i < 64; i++){ h[i] = act[i*SACT + p]; s += h[i]; }
    float m = s * (1.f/64.f);
    float v = 0.f;
#pragma unroll
    for (int i = 0; i < 64; i++){ float d = h[i]-m; v += d*d; }
    v *= (1.f/64.f);
    float rs = rsqrtf(v + 1e-5f);
#pragma unroll
    for (int i = 0; i < 64; i++)
        r[i*SACT + p] = fmaxf((h[i]-m)*rs*g[i] + be[i], 0.f);
}

// GEMM: aout[j][p] = bias[j] + sum_i rin[i][p]*w[i][j].
// Thread (tp=tid>>3, tj=tid&7): 8 positions (tp*8..+7, packed in f32x2 pairs)
// x 8 outputs (j = tj + 8v, interleaved for conflict-free weight loads).
__device__ __forceinline__ void dpb_gemm(const float* __restrict__ rin, float* __restrict__ aout,
                                         const float* __restrict__ w, const float* __restrict__ bias,
                                         int tid){
    int tp = tid >> 3;
    int tj = tid & 7;
    u64 acc[4][8];
#pragma unroll
    for (int v = 0; v < 8; v++){
        float bj = bias[tj + 8*v];
        u64 bp = pk2(bj, bj);
#pragma unroll
        for (int u2 = 0; u2 < 4; u2++) acc[u2][v] = bp;
    }
    for (int i = 0; i < 64; i++){
        u64 a2[4];
        const u64* ar = reinterpret_cast<const u64*>(&rin[i*SACT + tp*8]);
#pragma unroll
        for (int u2 = 0; u2 < 4; u2++) a2[u2] = ar[u2];
#pragma unroll
        for (int v = 0; v < 8; v++){
            float wv = w[i*64 + tj + 8*v];
            u64 wp = pk2(wv, wv);
#pragma unroll
            for (int u2 = 0; u2 < 4; u2++) acc[u2][v] = fma2(a2[u2], wp, acc[u2][v]);
        }
    }
#pragma unroll
    for (int v = 0; v < 8; v++)
#pragma unroll
        for (int u2 = 0; u2 < 4; u2++)
            *reinterpret_cast<u64*>(&aout[(tj + 8*v)*SACT + tp*8 + 2*u2]) = acc[u2][v];
}

__global__ __launch_bounds__(128) void dpb_kernel(
    const float* __restrict__ w0,  const float* __restrict__ b0_,
    const float* __restrict__ g1,  const float* __restrict__ be1,
    const float* __restrict__ w1,  const float* __restrict__ b1,
    const float* __restrict__ g2,  const float* __restrict__ be2,
    const float* __restrict__ w2,  const float* __restrict__ b2,
    const float* __restrict__ g3,  const float* __restrict__ be3,
    const float* __restrict__ w3,  const float* __restrict__ b3)
{
    extern __shared__ float smf[];
    float* sw1 = smf + OFF_SW1;
    float* sw2 = smf + OFF_SW2;
    float* sw3 = smf + OFF_SW3;
    float* sv  = smf + OFF_SV;
    float* act = smf + OFF_ACT;
    float* r   = smf + OFF_R;
    int tid = threadIdx.x;

    for (int i = tid; i < 4096; i += 128){ sw1[i] = w1[i]; sw2[i] = w2[i]; }
    for (int i = tid; i < 1024; i += 128) sw3[i] = w3[i];
    if (tid < 64){
        sv[0*64+tid]=w0[tid];  sv[1*64+tid]=b0_[tid];
        sv[2*64+tid]=g1[tid];  sv[3*64+tid]=be1[tid]; sv[4*64+tid]=b1[tid];
        sv[5*64+tid]=g2[tid];  sv[6*64+tid]=be2[tid]; sv[7*64+tid]=b2[tid];
        sv[8*64+tid]=g3[tid];  sv[9*64+tid]=be3[tid];
        if (tid < HEADS) sv[10*64+tid] = b3[tid];
    }
    __syncthreads();

    // layer 0: act[i][p] = idx(p)*w0[i] + b0[i]
    {
        int i  = tid >> 1;
        int ph = (tid & 1) * 64;
        float w0i = sv[i], b0i = sv[64+i];
        int base = blockIdx.x * 128;
        const float scale = 1.0f / (4095.0f * 64.0f);
        for (int q = 0; q < 64; q += 2){
            float vals[2];
#pragma unroll
            for (int z = 0; z < 2; z++){
                int id = base + ph + q + z;
                int pp = id & (NPOS-1);
                int d  = id >> 13;
                float idx;
                if (pp == 0 || pp == 4096)      idx = 0.0f;
                else if (pp < 4096)             idx =  (float)((pp-1)*64 + d + 1) * scale;
                else                            idx = -(float)(4095*64 - ((pp-4097)*64 + d)) * scale;
                vals[z] = idx * w0i + b0i;
            }
            *reinterpret_cast<u64*>(&act[i*SACT + ph + q]) = pk2(vals[0], vals[1]);
        }
    }
    __syncthreads();

    // layer 1
    dpb_ln(act, r, sv+2*64, sv+3*64, tid);  __syncthreads();
    dpb_gemm(r, act, sw1, sv+4*64, tid);    __syncthreads();
    // layer 2
    dpb_ln(act, r, sv+5*64, sv+6*64, tid);  __syncthreads();
    dpb_gemm(r, act, sw2, sv+7*64, tid);    __syncthreads();

    // layer 3: per-position LN + 64x16 GEMV
    {
        int p = tid;
        float h[64];
        float s = 0.f;
#pragma unroll
        for (int i = 0; i < 64; i++){ h[i] = act[i*SACT + p]; s += h[i]; }
        float m = s * (1.f/64.f);
        float v = 0.f;
#pragma unroll
        for (int i = 0; i < 64; i++){ float dd = h[i]-m; v += dd*dd; }
        v *= (1.f/64.f);
        float rs = rsqrtf(v + 1e-5f);

        u64 o[HEADS/2];
        const u64* b3u = reinterpret_cast<const u64*>(sv + 10*64);
#pragma unroll
        for (int j = 0; j < HEADS/2; j++) o[j] = b3u[j];
        for (int i = 0; i < 64; i++){
            float rr = fmaxf((h[i]-m)*rs*sv[8*64+i] + sv[9*64+i], 0.f);
            u64 rp = pk2(rr, rr);
            const ulonglong2* wr = reinterpret_cast<const ulonglong2*>(&sw3[i*HEADS]);
#pragma unroll
            for (int jq = 0; jq < 4; jq++){
                ulonglong2 wv2 = wr[jq];
                o[2*jq]   = fma2(rp, wv2.x, o[2*jq]);
                o[2*jq+1] = fma2(rp, wv2.y, o[2*jq+1]);
            }
        }
        int id = blockIdx.x*128 + tid;
        int pp = id & (NPOS-1);
        int d  = id >> 13;
#pragma unroll
        for (int j = 0; j < HEADS/2; j++){
            float lo, hi;
            upk2(o[j], lo, hi);
            g_abuf[(size_t)((2*j+0)*64 + d) * NPOS + pp] = lo;
            g_abuf[(size_t)((2*j+1)*64 + d) * NPOS + pp] = hi;
        }
    }
}

// ------------------------- A spectrum -------------------------
__device__ __forceinline__ void spectralA(const float2* __restrict__ Z, float2* __restrict__ Arow,
                                          int k, float2 T){
    int k2 = 4096 - k;
    float2 Zk = Z[SW(k)], Zk2 = Z[SW(k2)];
    float2 E  = make_float2((Zk.x+Zk2.x)*0.5f, (Zk.y-Zk2.y)*0.5f);
    float2 Dm = make_float2((Zk.x-Zk2.x)*0.5f, (Zk.y+Zk2.y)*0.5f);
    float2 O  = make_float2(Dm.y, -Dm.x);                    // -i*Dm
    float2 TO = cmul(T, O);
    Arow[k]  = make_float2(E.x+TO.x,  E.y+TO.y);
    Arow[k2] = make_float2(E.x-TO.x, -(E.y-TO.y));           // conj(E - T*O)
}

#define DLT make_float2(0.98078528040323044f, -0.19509032201612827f)

__global__ __launch_bounds__(256) void fft_a_kernel(){
    extern __shared__ float2 buf[];
    int t = threadIdx.x;
    int col = blockIdx.x;
    const float2* src = reinterpret_cast<const float2*>(g_abuf + (size_t)col * NPOS);
#pragma unroll
    for (int it = 0; it < 16; it++){
        int k = t + it*256;
        buf[SW(k)] = src[k];
    }
    __syncthreads();
    fft_stage16_sb<-1>(buf, 4096,   1, t);
    fft_stage16_sb<-1>(buf,  256,  16, t);
    fft_stage16_sb<-1>(buf,   16, 256, t);

    float2* Arow = g_Aspec + (size_t)col * ASTR;
    float sn, cs;
    __sincosf(-7.6699039394282068e-4f * (float)t, &sn, &cs);
    float2 T = make_float2(cs, sn);
#pragma unroll
    for (int it = 0; it < 8; it++){
        int k = t + it*256;
        if (k == 0){
            float2 Z0 = buf[SW(0)];
            Arow[0]    = make_float2(Z0.x + Z0.y, 0.f);
            Arow[4096] = make_float2(Z0.x - Z0.y, 0.f);
        } else {
            spectralA(buf, Arow, k, T);
        }
        T = cmul(T, DLT);
    }
    if (t == 0) spectralA(buf, Arow, 2048, make_float2(0.f, -1.f));
}

// ------------------------- transposes -------------------------
__global__ __launch_bounds__(256) void transpose_fwd(const float* __restrict__ in){
    __shared__ float tile[32][33];
    int d0 = blockIdx.x*32, n0 = blockIdx.y*32, bh = blockIdx.z;
    const float* src = in + (size_t)bh * SEQ * DIM;
#pragma unroll
    for (int j = 0; j < 4; j++)
        tile[threadIdx.y + 8*j][threadIdx.x] = src[(size_t)(n0 + threadIdx.y + 8*j)*DIM + d0 + threadIdx.x];
    __syncthreads();
    float* dst = g_xt + (size_t)bh * DIM * SEQ;
#pragma unroll
    for (int j = 0; j < 4; j++)
        dst[(size_t)(d0 + threadIdx.y + 8*j)*SEQ + n0 + threadIdx.x] = tile[threadIdx.x][threadIdx.y + 8*j];
}

__global__ __launch_bounds__(256) void transpose_back(float* __restrict__ out){
    __shared__ float tile[32][33];
    int d0 = blockIdx.x*32, n0 = blockIdx.y*32, bh = blockIdx.z;
    const float* src = g_xt + (size_t)bh * DIM * SEQ;
#pragma unroll
    for (int j = 0; j < 4; j++)
        tile[threadIdx.y + 8*j][threadIdx.x] = src[(size_t)(d0 + threadIdx.y + 8*j)*SEQ + n0 + threadIdx.x];
    __syncthreads();
    float* dst = out + (size_t)bh * SEQ * DIM;
#pragma unroll
    for (int j = 0; j < 4; j++)
        dst[(size_t)(n0 + threadIdx.y + 8*j)*DIM + d0 + threadIdx.x] = tile[threadIdx.x][threadIdx.y + 8*j];
}

// ------------------------- x conv -------------------------
__device__ __forceinline__ void spectralX(float2* __restrict__ Z, const float2* __restrict__ Arow,
                                          int k, float2 T){
    int k2 = 4096 - k;
    float2 Zk = Z[SW(k)], Zk2 = Z[SW(k2)];
    float2 E  = make_float2((Zk.x+Zk2.x)*0.5f, (Zk.y-Zk2.y)*0.5f);
    float2 Dm = make_float2((Zk.x-Zk2.x)*0.5f, (Zk.y+Zk2.y)*0.5f);
    float2 O  = make_float2(Dm.y, -Dm.x);
    float2 TO = cmul(T, O);
    float2 Y  = make_float2(E.x+TO.x,  E.y+TO.y);
    float2 Y2 = make_float2(E.x-TO.x, -(E.y-TO.y));
    float2 W  = cmul(Y,  Arow[k]);
    float2 W2 = cmul(Y2, Arow[k2]);
    float2 Ep = make_float2((W.x+W2.x)*0.5f, (W.y-W2.y)*0.5f);
    float2 Dp = make_float2((W.x-W2.x)*0.5f, (W.y+W2.y)*0.5f);
    float2 Op = cmul(make_float2(T.x, -T.y), Dp);            // conj(T)*Dp
    Z[SW(k)]  = make_float2(Ep.x - Op.y,  Ep.y + Op.x);
    Z[SW(k2)] = make_float2(Ep.x + Op.y, -Ep.y + Op.x);
}

__global__ __launch_bounds__(256, 3) void fft_x_kernel(){
    extern __shared__ float2 buf[];
    int t = threadIdx.x;
    int e = blockIdx.x;          // b innermost -> 8 CTAs reuse one A row in L2
    int b  = e & 7;
    int hd = e >> 3;
    int h  = hd >> 6;
    int d  = hd & 63;
    int bh = b * HEADS + h;
    float2* col = reinterpret_cast<float2*>(g_xt + ((size_t)bh * DIM + d) * SEQ);

    // forward stage 1 direct from gmem (upper half is zero pad)
    {
        float2 a[16];
#pragma unroll
        for (int k = 0; k < 8; k++) a[k] = col[t + 256*k];
        dft16_half<-1>(a);
        twiddle16<-1>(a, t, 4096);
#pragma unroll
        for (int k = 0; k < 16; k++) buf[SW(16*t + k)] = a[k];
    }
    __syncthreads();
    fft_stage16_sb<-1>(buf, 256,  16, t);
    fft_stage16_sb<-1>(buf,  16, 256, t);    // forward result, natural order

    const float2* Arow = g_Aspec + (size_t)hd * ASTR;
    {
        float sn, cs;
        __sincosf(-7.6699039394282068e-4f * (float)t, &sn, &cs);
        float2 T = make_float2(cs, sn);
#pragma unroll
        for (int it = 0; it < 8; it++){
            int k = t + it*256;
            if (k == 0){
                float2 Z0 = buf[SW(0)];
                float Y0 = Z0.x + Z0.y;
                float Y4 = Z0.x - Z0.y;
                float W0 = Y0*Arow[0].x;
                float W4 = Y4*Arow[4096].x;
                buf[SW(0)] = make_float2((W0+W4)*0.5f, (W0-W4)*0.5f);
            } else {
                spectralX(buf, Arow, k, T);
            }
            T = cmul(T, DLT);
        }
        if (t == 0) spectralX(buf, Arow, 2048, make_float2(0.f, -1.f));
    }
    __syncthreads();

    fft_stage16_sb<1>(buf, 4096,  1, t);
    fft_stage16_sb<1>(buf,  256, 16, t);
    // inverse stage 3: p=0 (no twiddle), only k<8 outputs kept -> straight to gmem
    {
        float2 a[16];
#pragma unroll
        for (int k = 0; k < 16; k++) a[k] = buf[SW(t + 256*k)];
        dft16<1>(a);
        const float inv = 1.f / 4096.f;
#pragma unroll
        for (int k = 0; k < 8; k++)
            col[t + 256*k] = make_float2(a[k].x * inv, a[k].y * inv);
    }
}

extern "C" void kernel_launch(void* const* d_in, const int* in_sizes, int n_in,
                              void* d_out, int out_size) {
    (void)in_sizes; (void)n_in; (void)out_size;
    const float* x   = (const float*)d_in[0];
    const float* w0  = (const float*)d_in[1];
    const float* b0_ = (const float*)d_in[2];
    const float* g1  = (const float*)d_in[3];
    const float* be1 = (const float*)d_in[4];
    const float* w1  = (const float*)d_in[5];
    const float* b1  = (const float*)d_in[6];
    const float* g2  = (const float*)d_in[7];
    const float* be2 = (const float*)d_in[8];
    const float* w2  = (const float*)d_in[9];
    const float* b2  = (const float*)d_in[10];
    const float* g3  = (const float*)d_in[11];
    const float* be3 = (const float*)d_in[12];
    const float* w3  = (const float*)d_in[13];
    const float* b3  = (const float*)d_in[14];
    float* out = (float*)d_out;

    static bool attr_done = false;
    if (!attr_done) {
        cudaFuncSetAttribute(dpb_kernel,  cudaFuncAttributeMaxDynamicSharedMemorySize, DPB_SMEM_BYTES);
        cudaFuncSetAttribute(fft_a_kernel, cudaFuncAttributeMaxDynamicSharedMemorySize, FFT_SMEM_BYTES);
        cudaFuncSetAttribute(fft_x_kernel, cudaFuncAttributeMaxDynamicSharedMemorySize, FFT_SMEM_BYTES);
        attr_done = true;
    }

    // 1. MLP -> a coefficients (tiled GEMM, 128 positions per CTA)
    dpb_kernel<<<(NPOS*DIM)/128, 128, DPB_SMEM_BYTES>>>(w0,b0_,g1,be1,w1,b1,g2,be2,w2,b2,g3,be3,w3,b3);
    // 2. A spectrum per (h,d)
    fft_a_kernel<<<NCOLS_A, 256, FFT_SMEM_BYTES>>>();
    // 3. transpose x -> [bh][d][n]
    {
        dim3 g(DIM/32, SEQ/32, 128), t(32, 8);
        transpose_fwd<<<g, t>>>(x);
    }
    // 4. FFT conv per column, in place
    fft_x_kernel<<<8 * NCOLS_A, 256, FFT_SMEM_BYTES>>>();
    // 5. transpose back -> out
    {
        dim3 g(DIM/32, SEQ/32, 128), t(32, 8);
        transpose_back<<<g, t>>>(out);
    }
}